// round 10
// baseline (speedup 1.0000x reference)
#include <cuda_runtime.h>
#include <cuda_fp16.h>
#include <stdint.h>

#define N_NODES 50000
#define E_EDGES 800000
#define D 128
#define SCAN_B 512
#define NBLK ((N_NODES + SCAN_B - 1) / SCAN_B)   // 98
#define GTILES ((N_NODES + 127) / 128)           // 391
#define GS 136                                    // smem f16 stride (bank-safe)

// ---------------------------------------------------------------------------
// Scratch (__device__ globals; zero-initialized at module load; no allocs).
// ---------------------------------------------------------------------------
__device__ __half g_Wh0[(size_t)N_NODES * D];
__device__ __half g_Wh1[(size_t)N_NODES * D];
__device__ int   g_cnt0[N_NODES];     // re-zeroed by fill_kernel each call
__device__ int   g_cnt1[N_NODES];
__device__ int   g_offs0[N_NODES];    // scan writes starts; fill bumps to ends
__device__ int   g_offs1[N_NODES];
__device__ int   g_srt0[E_EDGES];
__device__ int   g_srt1[E_EDGES];
__device__ int   g_bsum0[NBLK];
__device__ int   g_bsum1[NBLK];

// ---------------------------------------------------------------------------
// Host-side stream/event resources (created once; host-only resources).
// ---------------------------------------------------------------------------
struct Streams {
    cudaStream_t s1, s2;            // s1: GEMM, s2: relation-1 CSR chain
    cudaEvent_t  fork, evGemm, evFill1;
    Streams() {
        cudaStreamCreateWithFlags(&s1, cudaStreamNonBlocking);
        cudaStreamCreateWithFlags(&s2, cudaStreamNonBlocking);
        cudaEventCreateWithFlags(&fork,    cudaEventDisableTiming);
        cudaEventCreateWithFlags(&evGemm,  cudaEventDisableTiming);
        cudaEventCreateWithFlags(&evFill1, cudaEventDisableTiming);
    }
};
static Streams g_st;

// ---------------------------------------------------------------------------
// Warp-level HMMA m16n8k16 (sm_80+ baseline PTX).
// ---------------------------------------------------------------------------
__device__ __forceinline__ void mma16816(float* d,
                                         uint32_t a0, uint32_t a1,
                                         uint32_t a2, uint32_t a3,
                                         uint32_t b0, uint32_t b1) {
    asm volatile(
        "mma.sync.aligned.m16n8k16.row.col.f32.f16.f16.f32 "
        "{%0,%1,%2,%3}, {%4,%5,%6,%7}, {%8,%9}, {%0,%1,%2,%3};"
        : "+f"(d[0]), "+f"(d[1]), "+f"(d[2]), "+f"(d[3])
        : "r"(a0), "r"(a1), "r"(a2), "r"(a3), "r"(b0), "r"(b1));
}

// ---------------------------------------------------------------------------
// HMMA GEMM: Wh = fp16(feat @ W + b), Markidis hi/lo split. Stream s1.
// ---------------------------------------------------------------------------
__global__ __launch_bounds__(256, 1) void mma_gemm_kernel(
    const float* __restrict__ feat,
    const float* __restrict__ W0, const float* __restrict__ b0,
    const float* __restrict__ W1, const float* __restrict__ b1)
{
    extern __shared__ __align__(16) char smem[];
    __half* sAh = reinterpret_cast<__half*>(smem);
    __half* sAl = sAh + 128 * GS;
    __half* sBh = sAl + 128 * GS;
    __half* sBl = sBh + 128 * GS;

    const int rel = blockIdx.y;
    const float* __restrict__ W    = rel ? W1 : W0;
    const float* __restrict__ bias = rel ? b1 : b0;
    __half* __restrict__ Wh = rel ? g_Wh1 : g_Wh0;

    const int tid  = threadIdx.x;
    const int row0 = blockIdx.x * 128;

    for (int i = tid; i < D * D; i += 256) {
        const int k = i >> 7, n = i & 127;
        const float w = __ldg(W + i);
        const __half h = __float2half_rn(w);
        const __half l = __float2half_rn(w - __half2float(h));
        sBh[n * GS + k] = h;
        sBl[n * GS + k] = l;
    }
    for (int i = tid; i < 128 * D; i += 256) {
        const int r = i >> 7, k = i & 127;
        const int gr = row0 + r;
        const float a = (gr < N_NODES) ? __ldg(feat + (size_t)gr * D + k) : 0.f;
        const __half h = __float2half_rn(a);
        const __half l = __float2half_rn(a - __half2float(h));
        sAh[r * GS + k] = h;
        sAl[r * GS + k] = l;
    }
    __syncthreads();

    const int wid   = tid >> 5;
    const int lane  = tid & 31;
    const int group = lane >> 2;
    const int quad  = lane & 3;
    const int rA    = wid * 16 + group;

    float acc[16][4];
#pragma unroll
    for (int nt = 0; nt < 16; nt++)
#pragma unroll
        for (int j = 0; j < 4; j++) acc[nt][j] = 0.f;

#pragma unroll
    for (int kc = 0; kc < 8; kc++) {
        const int k0 = kc * 16 + quad * 2;
        const uint32_t ah0 = *reinterpret_cast<const uint32_t*>(&sAh[rA * GS + k0]);
        const uint32_t ah1 = *reinterpret_cast<const uint32_t*>(&sAh[(rA + 8) * GS + k0]);
        const uint32_t ah2 = *reinterpret_cast<const uint32_t*>(&sAh[rA * GS + k0 + 8]);
        const uint32_t ah3 = *reinterpret_cast<const uint32_t*>(&sAh[(rA + 8) * GS + k0 + 8]);
        const uint32_t al0 = *reinterpret_cast<const uint32_t*>(&sAl[rA * GS + k0]);
        const uint32_t al1 = *reinterpret_cast<const uint32_t*>(&sAl[(rA + 8) * GS + k0]);
        const uint32_t al2 = *reinterpret_cast<const uint32_t*>(&sAl[rA * GS + k0 + 8]);
        const uint32_t al3 = *reinterpret_cast<const uint32_t*>(&sAl[(rA + 8) * GS + k0 + 8]);
#pragma unroll
        for (int nt = 0; nt < 16; nt++) {
            const int n = nt * 8 + group;
            const uint32_t bh0 = *reinterpret_cast<const uint32_t*>(&sBh[n * GS + k0]);
            const uint32_t bh1 = *reinterpret_cast<const uint32_t*>(&sBh[n * GS + k0 + 8]);
            const uint32_t bl0 = *reinterpret_cast<const uint32_t*>(&sBl[n * GS + k0]);
            const uint32_t bl1 = *reinterpret_cast<const uint32_t*>(&sBl[n * GS + k0 + 8]);
            mma16816(acc[nt], ah0, ah1, ah2, ah3, bh0, bh1);
            mma16816(acc[nt], ah0, ah1, ah2, ah3, bl0, bl1);
            mma16816(acc[nt], al0, al1, al2, al3, bh0, bh1);
        }
    }

    const int r0 = row0 + rA;
    const int r1 = r0 + 8;
#pragma unroll
    for (int nt = 0; nt < 16; nt++) {
        const int c = nt * 8 + quad * 2;
        const float bx = __ldg(bias + c);
        const float by = __ldg(bias + c + 1);
        if (r0 < N_NODES) {
            __half2 h = __floats2half2_rn(acc[nt][0] + bx, acc[nt][1] + by);
            *reinterpret_cast<uint32_t*>(Wh + (size_t)r0 * D + c) =
                *reinterpret_cast<uint32_t*>(&h);
        }
        if (r1 < N_NODES) {
            __half2 h = __floats2half2_rn(acc[nt][2] + bx, acc[nt][3] + by);
            *reinterpret_cast<uint32_t*>(Wh + (size_t)r1 * D + c) =
                *reinterpret_cast<uint32_t*>(&h);
        }
    }
}

#define GEMM_SMEM (4 * 128 * GS * (int)sizeof(__half))

// ---------------------------------------------------------------------------
// Per-relation CSR kernels (rel selects globals inside).
// ---------------------------------------------------------------------------
__global__ __launch_bounds__(256) void hist_kernel(
    const int* __restrict__ dst, int rel)
{
    const int e0 = (blockIdx.x * blockDim.x + threadIdx.x) * 4;
    if (e0 >= E_EDGES) return;
    int* __restrict__ cnt = rel ? g_cnt1 : g_cnt0;
    const int4 d = __ldg(reinterpret_cast<const int4*>(dst + e0));
    atomicAdd(&cnt[d.x], 1);
    atomicAdd(&cnt[d.y], 1);
    atomicAdd(&cnt[d.z], 1);
    atomicAdd(&cnt[d.w], 1);
}

__global__ __launch_bounds__(SCAN_B) void scan_bsum_kernel(int rel) {
    const int* __restrict__ cnt = rel ? g_cnt1 : g_cnt0;
    int* __restrict__ bsum = rel ? g_bsum1 : g_bsum0;

    const int i = blockIdx.x * SCAN_B + threadIdx.x;
    int x = (i < N_NODES) ? cnt[i] : 0;
#pragma unroll
    for (int o = 16; o; o >>= 1) x += __shfl_down_sync(0xffffffffu, x, o);

    __shared__ int ws[SCAN_B / 32];
    const int lane = threadIdx.x & 31, wid = threadIdx.x >> 5;
    if (lane == 0) ws[wid] = x;
    __syncthreads();
    if (wid == 0) {
        int t = (lane < SCAN_B / 32) ? ws[lane] : 0;
#pragma unroll
        for (int o = 16; o; o >>= 1) t += __shfl_down_sync(0xffffffffu, t, o);
        if (lane == 0) bsum[blockIdx.x] = t;
    }
}

__global__ __launch_bounds__(SCAN_B) void scan_final_kernel(int rel) {
    const int* __restrict__ cnt  = rel ? g_cnt1  : g_cnt0;
    const int* __restrict__ bsum = rel ? g_bsum1 : g_bsum0;
    int* __restrict__ offs = rel ? g_offs1 : g_offs0;

    const int lane = threadIdx.x & 31, wid = threadIdx.x >> 5;

    __shared__ int sred[SCAN_B / 32];
    int v = (threadIdx.x < blockIdx.x) ? bsum[threadIdx.x] : 0;
#pragma unroll
    for (int o = 16; o; o >>= 1) v += __shfl_down_sync(0xffffffffu, v, o);
    if (lane == 0) sred[wid] = v;
    __syncthreads();
    if (threadIdx.x == 0) {
        int t = 0;
#pragma unroll
        for (int w = 0; w < SCAN_B / 32; w++) t += sred[w];
        sred[0] = t;
    }
    __syncthreads();
    const int base = sred[0];
    __syncthreads();

    const int i = blockIdx.x * SCAN_B + threadIdx.x;
    const int x = (i < N_NODES) ? cnt[i] : 0;
    int s = x;
#pragma unroll
    for (int o = 1; o < 32; o <<= 1) {
        int t = __shfl_up_sync(0xffffffffu, s, o);
        if (lane >= o) s += t;
    }
    __shared__ int ws[SCAN_B / 32];
    if (lane == 31) ws[wid] = s;
    __syncthreads();
    if (wid == 0) {
        int t = (lane < SCAN_B / 32) ? ws[lane] : 0;
#pragma unroll
        for (int o = 1; o < 32; o <<= 1) {
            int u = __shfl_up_sync(0xffffffffu, t, o);
            if (lane >= o) t += u;
        }
        if (lane < SCAN_B / 32) ws[lane] = t;
    }
    __syncthreads();
    const int prefix = (wid > 0) ? ws[wid - 1] : 0;
    if (i < N_NODES) offs[i] = base + prefix + s - x;
}

// Fill: atomicAdd on offs (post-fill offs[n] = segment end); re-zeroes cnt.
__global__ __launch_bounds__(256) void fill_kernel(
    const int* __restrict__ src, const int* __restrict__ dst, int rel)
{
    const int gt = blockIdx.x * blockDim.x + threadIdx.x;
    int* __restrict__ cnt = rel ? g_cnt1 : g_cnt0;
    if (gt < N_NODES) cnt[gt] = 0;

    const int e0 = gt * 4;
    if (e0 >= E_EDGES) return;
    int* __restrict__ offs = rel ? g_offs1 : g_offs0;
    int* __restrict__ srt  = rel ? g_srt1  : g_srt0;

    const int4 d = __ldg(reinterpret_cast<const int4*>(dst + e0));
    const int4 s = __ldg(reinterpret_cast<const int4*>(src + e0));
    const int p0 = atomicAdd(&offs[d.x], 1);
    const int p1 = atomicAdd(&offs[d.y], 1);
    const int p2 = atomicAdd(&offs[d.z], 1);
    const int p3 = atomicAdd(&offs[d.w], 1);
    srt[p0] = s.x; srt[p1] = s.y; srt[p2] = s.z; srt[p3] = s.w;
}

// ---------------------------------------------------------------------------
// Per-relation warp-per-node gather (R8-proven shape: uint2/lane, unroll 8).
// ADD=0: out = mean; ADD=1: out += mean.
// ---------------------------------------------------------------------------
__device__ __forceinline__ void acc_u2(float4& a, uint2 u) {
    const __half2 h0 = *reinterpret_cast<__half2*>(&u.x);
    const __half2 h1 = *reinterpret_cast<__half2*>(&u.y);
    const float2 f0 = __half22float2(h0);
    const float2 f1 = __half22float2(h1);
    a.x += f0.x; a.y += f0.y; a.z += f1.x; a.w += f1.y;
}
__device__ __forceinline__ uint2 ld_row_h(const __half* __restrict__ Wh,
                                          int s, int lane) {
    return __ldg(reinterpret_cast<const uint2*>(Wh + (size_t)s * D) + lane);
}
__device__ __forceinline__ float4 gather_rel(
    const __half* __restrict__ Wh, const int* __restrict__ srt,
    int beg, int end, int lane)
{
    float4 acc = make_float4(0.f, 0.f, 0.f, 0.f);
    int e = beg;
    for (; e + 8 <= end; e += 8) {
        int s[8];
#pragma unroll
        for (int j = 0; j < 8; j++) s[j] = __ldg(srt + e + j);
        uint2 u[8];
#pragma unroll
        for (int j = 0; j < 8; j++) u[j] = ld_row_h(Wh, s[j], lane);
#pragma unroll
        for (int j = 0; j < 8; j++) acc_u2(acc, u[j]);
    }
    if (e + 4 <= end) {
        int s[4];
#pragma unroll
        for (int j = 0; j < 4; j++) s[j] = __ldg(srt + e + j);
        uint2 u[4];
#pragma unroll
        for (int j = 0; j < 4; j++) u[j] = ld_row_h(Wh, s[j], lane);
#pragma unroll
        for (int j = 0; j < 4; j++) acc_u2(acc, u[j]);
        e += 4;
    }
    for (; e < end; e++)
        acc_u2(acc, ld_row_h(Wh, __ldg(srt + e), lane));
    return acc;
}

template <int ADD>
__global__ __launch_bounds__(256) void gather_kernel(float* __restrict__ out,
                                                     int rel) {
    const int n = blockIdx.x * 8 + (threadIdx.x >> 5);
    if (n >= N_NODES) return;
    const int lane = threadIdx.x & 31;

    const __half* __restrict__ Wh  = rel ? g_Wh1  : g_Wh0;
    const int*    __restrict__ off = rel ? g_offs1 : g_offs0;
    const int*    __restrict__ srt = rel ? g_srt1  : g_srt0;

    const int end = __ldg(off + n);
    const int beg = n ? __ldg(off + n - 1) : 0;

    const float4 a = gather_rel(Wh, srt, beg, end, lane);
    const float inv = 1.0f / fmaxf((float)(end - beg), 1.0f);

    float4* op = reinterpret_cast<float4*>(out + (size_t)n * D) + lane;
    float4 r;
    if (ADD) {
        const float4 prev = *op;
        r.x = prev.x + a.x * inv;
        r.y = prev.y + a.y * inv;
        r.z = prev.z + a.z * inv;
        r.w = prev.w + a.w * inv;
    } else {
        r.x = a.x * inv;
        r.y = a.y * inv;
        r.z = a.z * inv;
        r.w = a.w * inv;
    }
    *op = r;
}

// ---------------------------------------------------------------------------
// inputs: feat, W0, b0, W1, b1, src0, dst0, src1, dst1
// ---------------------------------------------------------------------------
extern "C" void kernel_launch(void* const* d_in, const int* in_sizes, int n_in,
                              void* d_out, int out_size) {
    const float* feat = (const float*)d_in[0];
    const float* W0   = (const float*)d_in[1];
    const float* b0   = (const float*)d_in[2];
    const float* W1   = (const float*)d_in[3];
    const float* b1   = (const float*)d_in[4];
    const int*   src0 = (const int*)d_in[5];
    const int*   dst0 = (const int*)d_in[6];
    const int*   src1 = (const int*)d_in[7];
    const int*   dst1 = (const int*)d_in[8];
    float* out = (float*)d_out;

    cudaFuncSetAttribute(mma_gemm_kernel,
                         cudaFuncAttributeMaxDynamicSharedMemorySize, GEMM_SMEM);

    const int egrid = (E_EDGES / 4 + 255) / 256;   // 782 (covers N for cnt zero)
    const int ggrid = (N_NODES + 7) / 8;           // 6250

    // Fork both side streams from stream 0.
    cudaEventRecord(g_st.fork, 0);
    cudaStreamWaitEvent(g_st.s1, g_st.fork, 0);
    cudaStreamWaitEvent(g_st.s2, g_st.fork, 0);

    // s1: GEMM for both relations.
    dim3 gg(GTILES, 2);
    mma_gemm_kernel<<<gg, 256, GEMM_SMEM, g_st.s1>>>(feat, W0, b0, W1, b1);
    cudaEventRecord(g_st.evGemm, g_st.s1);

    // s2: relation-1 CSR chain.
    hist_kernel<<<egrid, 256, 0, g_st.s2>>>(dst1, 1);
    scan_bsum_kernel<<<NBLK, SCAN_B, 0, g_st.s2>>>(1);
    scan_final_kernel<<<NBLK, SCAN_B, 0, g_st.s2>>>(1);
    fill_kernel<<<egrid, 256, 0, g_st.s2>>>(src1, dst1, 1);
    cudaEventRecord(g_st.evFill1, g_st.s2);

    // stream 0: relation-0 CSR chain, then the two gathers.
    hist_kernel<<<egrid, 256>>>(dst0, 0);
    scan_bsum_kernel<<<NBLK, SCAN_B>>>(0);
    scan_final_kernel<<<NBLK, SCAN_B>>>(0);
    fill_kernel<<<egrid, 256>>>(src0, dst0, 0);

    cudaStreamWaitEvent(0, g_st.evGemm, 0);        // Wh0/Wh1 ready
    gather_kernel<0><<<ggrid, 256>>>(out, 0);      // out  = mean0
    cudaStreamWaitEvent(0, g_st.evFill1, 0);       // CSR1 ready
    gather_kernel<1><<<ggrid, 256>>>(out, 1);      // out += mean1
}

// round 11
// speedup vs baseline: 1.0616x; 1.0616x over previous
#include <cuda_runtime.h>
#include <cuda_fp16.h>
#include <stdint.h>

#define N_NODES 50000
#define E_EDGES 800000
#define D 128
#define CAP 128                                   // max in-degree slots per node
#define GTILES ((N_NODES + 127) / 128)            // 391
#define GS 136                                    // smem f16 stride (bank-safe)

// ---------------------------------------------------------------------------
// Scratch (__device__ globals; zero-initialized at module load; no allocs).
// g_cnt* are re-zeroed by gather_kernel after use -> every call starts clean.
// ---------------------------------------------------------------------------
__device__ __half g_Wh0[(size_t)N_NODES * D];
__device__ __half g_Wh1[(size_t)N_NODES * D];
__device__ int   g_cnt0[N_NODES];
__device__ int   g_cnt1[N_NODES];
__device__ int   g_srt0[(size_t)N_NODES * CAP];   // 25.6 MB
__device__ int   g_srt1[(size_t)N_NODES * CAP];

// ---------------------------------------------------------------------------
// Host-side stream/event resources (created once; host-only resources).
// ---------------------------------------------------------------------------
struct Streams {
    cudaStream_t s1;
    cudaEvent_t  fork, evGemm;
    Streams() {
        cudaStreamCreateWithFlags(&s1, cudaStreamNonBlocking);
        cudaEventCreateWithFlags(&fork,   cudaEventDisableTiming);
        cudaEventCreateWithFlags(&evGemm, cudaEventDisableTiming);
    }
};
static Streams g_st;

// ---------------------------------------------------------------------------
// Warp-level HMMA m16n8k16 (sm_80+ baseline PTX).
// ---------------------------------------------------------------------------
__device__ __forceinline__ void mma16816(float* d,
                                         uint32_t a0, uint32_t a1,
                                         uint32_t a2, uint32_t a3,
                                         uint32_t b0, uint32_t b1) {
    asm volatile(
        "mma.sync.aligned.m16n8k16.row.col.f32.f16.f16.f32 "
        "{%0,%1,%2,%3}, {%4,%5,%6,%7}, {%8,%9}, {%0,%1,%2,%3};"
        : "+f"(d[0]), "+f"(d[1]), "+f"(d[2]), "+f"(d[3])
        : "r"(a0), "r"(a1), "r"(a2), "r"(a3), "r"(b0), "r"(b1));
}

// ---------------------------------------------------------------------------
// HMMA GEMM: Wh = fp16(feat @ W + b), Markidis hi/lo split. Stream s1.
// ---------------------------------------------------------------------------
__global__ __launch_bounds__(256, 1) void mma_gemm_kernel(
    const float* __restrict__ feat,
    const float* __restrict__ W0, const float* __restrict__ b0,
    const float* __restrict__ W1, const float* __restrict__ b1)
{
    extern __shared__ __align__(16) char smem[];
    __half* sAh = reinterpret_cast<__half*>(smem);
    __half* sAl = sAh + 128 * GS;
    __half* sBh = sAl + 128 * GS;
    __half* sBl = sBh + 128 * GS;

    const int rel = blockIdx.y;
    const float* __restrict__ W    = rel ? W1 : W0;
    const float* __restrict__ bias = rel ? b1 : b0;
    __half* __restrict__ Wh = rel ? g_Wh1 : g_Wh0;

    const int tid  = threadIdx.x;
    const int row0 = blockIdx.x * 128;

    for (int i = tid; i < D * D; i += 256) {
        const int k = i >> 7, n = i & 127;
        const float w = __ldg(W + i);
        const __half h = __float2half_rn(w);
        const __half l = __float2half_rn(w - __half2float(h));
        sBh[n * GS + k] = h;
        sBl[n * GS + k] = l;
    }
    for (int i = tid; i < 128 * D; i += 256) {
        const int r = i >> 7, k = i & 127;
        const int gr = row0 + r;
        const float a = (gr < N_NODES) ? __ldg(feat + (size_t)gr * D + k) : 0.f;
        const __half h = __float2half_rn(a);
        const __half l = __float2half_rn(a - __half2float(h));
        sAh[r * GS + k] = h;
        sAl[r * GS + k] = l;
    }
    __syncthreads();

    const int wid   = tid >> 5;
    const int lane  = tid & 31;
    const int group = lane >> 2;
    const int quad  = lane & 3;
    const int rA    = wid * 16 + group;

    float acc[16][4];
#pragma unroll
    for (int nt = 0; nt < 16; nt++)
#pragma unroll
        for (int j = 0; j < 4; j++) acc[nt][j] = 0.f;

#pragma unroll
    for (int kc = 0; kc < 8; kc++) {
        const int k0 = kc * 16 + quad * 2;
        const uint32_t ah0 = *reinterpret_cast<const uint32_t*>(&sAh[rA * GS + k0]);
        const uint32_t ah1 = *reinterpret_cast<const uint32_t*>(&sAh[(rA + 8) * GS + k0]);
        const uint32_t ah2 = *reinterpret_cast<const uint32_t*>(&sAh[rA * GS + k0 + 8]);
        const uint32_t ah3 = *reinterpret_cast<const uint32_t*>(&sAh[(rA + 8) * GS + k0 + 8]);
        const uint32_t al0 = *reinterpret_cast<const uint32_t*>(&sAl[rA * GS + k0]);
        const uint32_t al1 = *reinterpret_cast<const uint32_t*>(&sAl[(rA + 8) * GS + k0]);
        const uint32_t al2 = *reinterpret_cast<const uint32_t*>(&sAl[rA * GS + k0 + 8]);
        const uint32_t al3 = *reinterpret_cast<const uint32_t*>(&sAl[(rA + 8) * GS + k0 + 8]);
#pragma unroll
        for (int nt = 0; nt < 16; nt++) {
            const int n = nt * 8 + group;
            const uint32_t bh0 = *reinterpret_cast<const uint32_t*>(&sBh[n * GS + k0]);
            const uint32_t bh1 = *reinterpret_cast<const uint32_t*>(&sBh[n * GS + k0 + 8]);
            const uint32_t bl0 = *reinterpret_cast<const uint32_t*>(&sBl[n * GS + k0]);
            const uint32_t bl1 = *reinterpret_cast<const uint32_t*>(&sBl[n * GS + k0 + 8]);
            mma16816(acc[nt], ah0, ah1, ah2, ah3, bh0, bh1);
            mma16816(acc[nt], ah0, ah1, ah2, ah3, bl0, bl1);
            mma16816(acc[nt], al0, al1, al2, al3, bh0, bh1);
        }
    }

    const int r0 = row0 + rA;
    const int r1 = r0 + 8;
#pragma unroll
    for (int nt = 0; nt < 16; nt++) {
        const int c = nt * 8 + quad * 2;
        const float bx = __ldg(bias + c);
        const float by = __ldg(bias + c + 1);
        if (r0 < N_NODES) {
            __half2 h = __floats2half2_rn(acc[nt][0] + bx, acc[nt][1] + by);
            *reinterpret_cast<uint32_t*>(Wh + (size_t)r0 * D + c) =
                *reinterpret_cast<uint32_t*>(&h);
        }
        if (r1 < N_NODES) {
            __half2 h = __floats2half2_rn(acc[nt][2] + bx, acc[nt][3] + by);
            *reinterpret_cast<uint32_t*>(Wh + (size_t)r1 * D + c) =
                *reinterpret_cast<uint32_t*>(&h);
        }
    }
}

#define GEMM_SMEM (4 * 128 * GS * (int)sizeof(__half))

// ---------------------------------------------------------------------------
// Bucket build: ONE kernel replaces hist+scan+fill. rank = atomicAdd(cnt),
// slot = dst*CAP + rank. cnt arrives zeroed (gather re-zeroes it after use).
// blockIdx.y selects relation.
// ---------------------------------------------------------------------------
__global__ __launch_bounds__(256) void bucket_kernel(
    const int* __restrict__ src0, const int* __restrict__ dst0,
    const int* __restrict__ src1, const int* __restrict__ dst1)
{
    const int e0 = (blockIdx.x * blockDim.x + threadIdx.x) * 4;
    if (e0 >= E_EDGES) return;
    const int* __restrict__ src = blockIdx.y ? src1 : src0;
    const int* __restrict__ dst = blockIdx.y ? dst1 : dst0;
    int* __restrict__ cnt = blockIdx.y ? g_cnt1 : g_cnt0;
    int* __restrict__ srt = blockIdx.y ? g_srt1 : g_srt0;

    const int4 d = __ldg(reinterpret_cast<const int4*>(dst + e0));
    const int4 s = __ldg(reinterpret_cast<const int4*>(src + e0));
    const int r0 = atomicAdd(&cnt[d.x], 1);
    const int r1 = atomicAdd(&cnt[d.y], 1);
    const int r2 = atomicAdd(&cnt[d.z], 1);
    const int r3 = atomicAdd(&cnt[d.w], 1);
    if (r0 < CAP) srt[(size_t)d.x * CAP + r0] = s.x;
    if (r1 < CAP) srt[(size_t)d.y * CAP + r1] = s.y;
    if (r2 < CAP) srt[(size_t)d.z * CAP + r2] = s.z;
    if (r3 < CAP) srt[(size_t)d.w * CAP + r3] = s.w;
}

// ---------------------------------------------------------------------------
// Warp-per-node pull gather over fp16 Wh (R8-proven shape: uint2/lane,
// unroll 8). Both relations per warp; re-zeroes cnt for the next call.
// ---------------------------------------------------------------------------
__device__ __forceinline__ void acc_u2(float4& a, uint2 u) {
    const __half2 h0 = *reinterpret_cast<__half2*>(&u.x);
    const __half2 h1 = *reinterpret_cast<__half2*>(&u.y);
    const float2 f0 = __half22float2(h0);
    const float2 f1 = __half22float2(h1);
    a.x += f0.x; a.y += f0.y; a.z += f1.x; a.w += f1.y;
}
__device__ __forceinline__ uint2 ld_row_h(const __half* __restrict__ Wh,
                                          int s, int lane) {
    return __ldg(reinterpret_cast<const uint2*>(Wh + (size_t)s * D) + lane);
}
__device__ __forceinline__ float4 gather_rel(
    const __half* __restrict__ Wh, const int* __restrict__ srt,
    int beg, int end, int lane)
{
    float4 acc = make_float4(0.f, 0.f, 0.f, 0.f);
    int e = beg;
    for (; e + 8 <= end; e += 8) {
        int s[8];
#pragma unroll
        for (int j = 0; j < 8; j++) s[j] = __ldg(srt + e + j);
        uint2 u[8];
#pragma unroll
        for (int j = 0; j < 8; j++) u[j] = ld_row_h(Wh, s[j], lane);
#pragma unroll
        for (int j = 0; j < 8; j++) acc_u2(acc, u[j]);
    }
    if (e + 4 <= end) {
        int s[4];
#pragma unroll
        for (int j = 0; j < 4; j++) s[j] = __ldg(srt + e + j);
        uint2 u[4];
#pragma unroll
        for (int j = 0; j < 4; j++) u[j] = ld_row_h(Wh, s[j], lane);
#pragma unroll
        for (int j = 0; j < 4; j++) acc_u2(acc, u[j]);
        e += 4;
    }
    for (; e < end; e++)
        acc_u2(acc, ld_row_h(Wh, __ldg(srt + e), lane));
    return acc;
}

__global__ __launch_bounds__(256) void gather_kernel(float* __restrict__ out) {
    const int n = blockIdx.x * 8 + (threadIdx.x >> 5);
    if (n >= N_NODES) return;
    const int lane = threadIdx.x & 31;

    const int d0 = __ldg(g_cnt0 + n);
    const int d1 = __ldg(g_cnt1 + n);
    const int beg0 = n * CAP, end0 = beg0 + min(d0, CAP);
    const int beg1 = n * CAP, end1 = beg1 + min(d1, CAP);

    const float4 a0 = gather_rel(g_Wh0, g_srt0, beg0, end0, lane);
    const float4 a1 = gather_rel(g_Wh1, g_srt1, beg1, end1, lane);

    // Reset counters for the next graph replay.
    if (lane == 0) { g_cnt0[n] = 0; g_cnt1[n] = 0; }

    const float inv0 = 1.0f / fmaxf((float)d0, 1.0f);
    const float inv1 = 1.0f / fmaxf((float)d1, 1.0f);

    float4 r;
    r.x = a0.x * inv0 + a1.x * inv1;
    r.y = a0.y * inv0 + a1.y * inv1;
    r.z = a0.z * inv0 + a1.z * inv1;
    r.w = a0.w * inv0 + a1.w * inv1;
    reinterpret_cast<float4*>(out + (size_t)n * D)[lane] = r;
}

// ---------------------------------------------------------------------------
// inputs: feat, W0, b0, W1, b1, src0, dst0, src1, dst1
// ---------------------------------------------------------------------------
extern "C" void kernel_launch(void* const* d_in, const int* in_sizes, int n_in,
                              void* d_out, int out_size) {
    const float* feat = (const float*)d_in[0];
    const float* W0   = (const float*)d_in[1];
    const float* b0   = (const float*)d_in[2];
    const float* W1   = (const float*)d_in[3];
    const float* b1   = (const float*)d_in[4];
    const int*   src0 = (const int*)d_in[5];
    const int*   dst0 = (const int*)d_in[6];
    const int*   src1 = (const int*)d_in[7];
    const int*   dst1 = (const int*)d_in[8];
    float* out = (float*)d_out;

    cudaFuncSetAttribute(mma_gemm_kernel,
                         cudaFuncAttributeMaxDynamicSharedMemorySize, GEMM_SMEM);

    // Fork: HMMA GEMM on side stream, concurrent with the bucket build.
    cudaEventRecord(g_st.fork, 0);
    cudaStreamWaitEvent(g_st.s1, g_st.fork, 0);
    dim3 gg(GTILES, 2);
    mma_gemm_kernel<<<gg, 256, GEMM_SMEM, g_st.s1>>>(feat, W0, b0, W1, b1);
    cudaEventRecord(g_st.evGemm, g_st.s1);

    // Main stream: single-kernel CSR-free bucket build (both relations).
    dim3 egrid4((E_EDGES / 4 + 255) / 256, 2);
    bucket_kernel<<<egrid4, 256>>>(src0, dst0, src1, dst1);

    // Join, then gather (also resets cnt for the next replay).
    cudaStreamWaitEvent(0, g_st.evGemm, 0);
    gather_kernel<<<(N_NODES + 7) / 8, 256>>>(out);
}

// round 12
// speedup vs baseline: 1.7129x; 1.6135x over previous
#include <cuda_runtime.h>
#include <cuda_fp16.h>
#include <stdint.h>

#define N_NODES 50000
#define E_EDGES 800000
#define D 128
#define CAP 128                                   // max in-degree slots per node
#define GTILES ((N_NODES + 127) / 128)            // 391
#define GS 136                                    // smem f16 stride (bank-safe)

// ---------------------------------------------------------------------------
// Scratch (__device__ globals; zero-initialized at module load; no allocs).
// ---------------------------------------------------------------------------
__device__ __half g_Wh0[(size_t)N_NODES * D];
__device__ __half g_Wh1[(size_t)N_NODES * D];
__device__ __half g_Bh0[D * D];                   // Wt hi/lo, fp16 [n][k]
__device__ __half g_Bl0[D * D];
__device__ __half g_Bh1[D * D];
__device__ __half g_Bl1[D * D];
__device__ int   g_cnt0[N_NODES];                 // re-zeroed by gather
__device__ int   g_cnt1[N_NODES];
__device__ int   g_srt0[(size_t)N_NODES * CAP];
__device__ int   g_srt1[(size_t)N_NODES * CAP];

// ---------------------------------------------------------------------------
// Host-side stream/event resources (created once; host-only resources).
// ---------------------------------------------------------------------------
struct Streams {
    cudaStream_t s1;
    cudaEvent_t  fork, evGemm;
    Streams() {
        cudaStreamCreateWithFlags(&s1, cudaStreamNonBlocking);
        cudaEventCreateWithFlags(&fork,   cudaEventDisableTiming);
        cudaEventCreateWithFlags(&evGemm, cudaEventDisableTiming);
    }
};
static Streams g_st;

// ---------------------------------------------------------------------------
// Warp-level HMMA m16n8k16 (sm_80+ baseline PTX).
// ---------------------------------------------------------------------------
__device__ __forceinline__ void mma16816(float* d,
                                         uint32_t a0, uint32_t a1,
                                         uint32_t a2, uint32_t a3,
                                         uint32_t b0, uint32_t b1) {
    asm volatile(
        "mma.sync.aligned.m16n8k16.row.col.f32.f16.f16.f32 "
        "{%0,%1,%2,%3}, {%4,%5,%6,%7}, {%8,%9}, {%0,%1,%2,%3};"
        : "+f"(d[0]), "+f"(d[1]), "+f"(d[2]), "+f"(d[3])
        : "r"(a0), "r"(a1), "r"(a2), "r"(a3), "r"(b0), "r"(b1));
}

__device__ __forceinline__ uint32_t h2u(__half2 h) {
    return *reinterpret_cast<uint32_t*>(&h);
}

// ---------------------------------------------------------------------------
// Prep: W (fp32 [k][n]) -> Wt hi/lo (fp16 [n][k]) once per call. Tiny.
// ---------------------------------------------------------------------------
__global__ __launch_bounds__(256) void prep_kernel(
    const float* __restrict__ W0, const float* __restrict__ W1)
{
    const int rel = blockIdx.y;
    const float* __restrict__ W = rel ? W1 : W0;
    __half* __restrict__ Bh = rel ? g_Bh1 : g_Bh0;
    __half* __restrict__ Bl = rel ? g_Bl1 : g_Bl0;
    const int i = blockIdx.x * 256 + threadIdx.x;   // < 16384
    const int n = i >> 7, k = i & 127;
    const float w = __ldg(W + k * D + n);
    const __half h = __float2half_rn(w);
    Bh[i] = h;
    Bl[i] = __float2half_rn(w - __half2float(h));
}

// ---------------------------------------------------------------------------
// HMMA GEMM v2: Wh = fp16(feat @ W + b), Markidis hi/lo split.
// B: smem (uint4-copied from precomputed fp16). A: streamed from global,
// converted in registers. 69.6 KB smem + <=124 regs => 2 blocks/SM.
// ---------------------------------------------------------------------------
__global__ __launch_bounds__(256, 2) void mma_gemm_kernel(
    const float* __restrict__ feat,
    const float* __restrict__ b0v, const float* __restrict__ b1v)
{
    extern __shared__ __align__(16) char smem[];
    __half* sBh = reinterpret_cast<__half*>(smem);         // [128][GS]
    __half* sBl = sBh + 128 * GS;

    const int rel = blockIdx.y;
    const float* __restrict__ bias = rel ? b1v : b0v;
    const __half* __restrict__ gBh = rel ? g_Bh1 : g_Bh0;
    const __half* __restrict__ gBl = rel ? g_Bl1 : g_Bl0;
    __half* __restrict__ Wh = rel ? g_Wh1 : g_Wh0;

    const int tid  = threadIdx.x;
    const int row0 = blockIdx.x * 128;

    // ---- Vectorized B fill: global fp16 -> smem (re-stride 128 -> GS) ----
    for (int i = tid; i < 128 * 16; i += 256) {
        const int n = i >> 4, c = i & 15;
        *reinterpret_cast<uint4*>(sBh + n * GS + c * 8) =
            *reinterpret_cast<const uint4*>(gBh + n * D + c * 8);
        *reinterpret_cast<uint4*>(sBl + n * GS + c * 8) =
            *reinterpret_cast<const uint4*>(gBl + n * D + c * 8);
    }
    __syncthreads();

    const int wid   = tid >> 5;
    const int lane  = tid & 31;
    const int group = lane >> 2;
    const int quad  = lane & 3;
    const int rA    = wid * 16 + group;
    const int r0 = row0 + rA;
    const int r1 = r0 + 8;
    const bool v0 = r0 < N_NODES;
    const bool v1 = r1 < N_NODES;
    const float2* __restrict__ f0 =
        reinterpret_cast<const float2*>(feat + (size_t)r0 * D);
    const float2* __restrict__ f1 =
        reinterpret_cast<const float2*>(feat + (size_t)r1 * D);

    float acc[16][4];
#pragma unroll
    for (int nt = 0; nt < 16; nt++)
#pragma unroll
        for (int j = 0; j < 4; j++) acc[nt][j] = 0.f;

    const float2 z2 = make_float2(0.f, 0.f);
#pragma unroll
    for (int kc = 0; kc < 8; kc++) {
        const int koff = kc * 8 + quad;            // float2 index (k0 = 2*koff)
        // A fragments straight from global (LDG.64, 8 full sectors/warp).
        const float2 x0 = v0 ? __ldg(f0 + koff)     : z2;
        const float2 x1 = v1 ? __ldg(f1 + koff)     : z2;
        const float2 x2 = v0 ? __ldg(f0 + koff + 4) : z2;
        const float2 x3 = v1 ? __ldg(f1 + koff + 4) : z2;
        // hi/lo split in registers.
        const __half2 h0 = __floats2half2_rn(x0.x, x0.y);
        const __half2 h1 = __floats2half2_rn(x1.x, x1.y);
        const __half2 h2 = __floats2half2_rn(x2.x, x2.y);
        const __half2 h3 = __floats2half2_rn(x3.x, x3.y);
        const __half2 l0 = __floats2half2_rn(x0.x - __low2float(h0),
                                             x0.y - __high2float(h0));
        const __half2 l1 = __floats2half2_rn(x1.x - __low2float(h1),
                                             x1.y - __high2float(h1));
        const __half2 l2 = __floats2half2_rn(x2.x - __low2float(h2),
                                             x2.y - __high2float(h2));
        const __half2 l3 = __floats2half2_rn(x3.x - __low2float(h3),
                                             x3.y - __high2float(h3));
        const uint32_t ah0 = h2u(h0), ah1 = h2u(h1), ah2 = h2u(h2), ah3 = h2u(h3);
        const uint32_t al0 = h2u(l0), al1 = h2u(l1), al2 = h2u(l2), al3 = h2u(l3);

        const int k0 = kc * 16 + quad * 2;
#pragma unroll
        for (int nt = 0; nt < 16; nt++) {
            const int n = nt * 8 + group;
            const uint32_t bh0 = *reinterpret_cast<const uint32_t*>(&sBh[n * GS + k0]);
            const uint32_t bh1 = *reinterpret_cast<const uint32_t*>(&sBh[n * GS + k0 + 8]);
            const uint32_t bl0 = *reinterpret_cast<const uint32_t*>(&sBl[n * GS + k0]);
            const uint32_t bl1 = *reinterpret_cast<const uint32_t*>(&sBl[n * GS + k0 + 8]);
            mma16816(acc[nt], ah0, ah1, ah2, ah3, bh0, bh1);
            mma16816(acc[nt], ah0, ah1, ah2, ah3, bl0, bl1);
            mma16816(acc[nt], al0, al1, al2, al3, bh0, bh1);
        }
    }

    // ---- Epilogue: bias add + fp16 store ----
#pragma unroll
    for (int nt = 0; nt < 16; nt++) {
        const int c = nt * 8 + quad * 2;
        const float bx = __ldg(bias + c);
        const float by = __ldg(bias + c + 1);
        if (v0) {
            __half2 h = __floats2half2_rn(acc[nt][0] + bx, acc[nt][1] + by);
            *reinterpret_cast<uint32_t*>(Wh + (size_t)r0 * D + c) = h2u(h);
        }
        if (v1) {
            __half2 h = __floats2half2_rn(acc[nt][2] + bx, acc[nt][3] + by);
            *reinterpret_cast<uint32_t*>(Wh + (size_t)r1 * D + c) = h2u(h);
        }
    }
}

#define GEMM_SMEM (2 * 128 * GS * (int)sizeof(__half))   // 69,632 B

// ---------------------------------------------------------------------------
// Bucket build: one kernel replaces hist+scan+fill. cnt arrives zeroed.
// ---------------------------------------------------------------------------
__global__ __launch_bounds__(256) void bucket_kernel(
    const int* __restrict__ src0, const int* __restrict__ dst0,
    const int* __restrict__ src1, const int* __restrict__ dst1)
{
    const int e0 = (blockIdx.x * blockDim.x + threadIdx.x) * 4;
    if (e0 >= E_EDGES) return;
    const int* __restrict__ src = blockIdx.y ? src1 : src0;
    const int* __restrict__ dst = blockIdx.y ? dst1 : dst0;
    int* __restrict__ cnt = blockIdx.y ? g_cnt1 : g_cnt0;
    int* __restrict__ srt = blockIdx.y ? g_srt1 : g_srt0;

    const int4 d = __ldg(reinterpret_cast<const int4*>(dst + e0));
    const int4 s = __ldg(reinterpret_cast<const int4*>(src + e0));
    const int r0 = atomicAdd(&cnt[d.x], 1);
    const int r1 = atomicAdd(&cnt[d.y], 1);
    const int r2 = atomicAdd(&cnt[d.z], 1);
    const int r3 = atomicAdd(&cnt[d.w], 1);
    if (r0 < CAP) srt[(size_t)d.x * CAP + r0] = s.x;
    if (r1 < CAP) srt[(size_t)d.y * CAP + r1] = s.y;
    if (r2 < CAP) srt[(size_t)d.z * CAP + r2] = s.z;
    if (r3 < CAP) srt[(size_t)d.w * CAP + r3] = s.w;
}

// ---------------------------------------------------------------------------
// Warp-per-node pull gather (R8-proven shape). Re-zeroes cnt after use.
// ---------------------------------------------------------------------------
__device__ __forceinline__ void acc_u2(float4& a, uint2 u) {
    const __half2 h0 = *reinterpret_cast<__half2*>(&u.x);
    const __half2 h1 = *reinterpret_cast<__half2*>(&u.y);
    const float2 f0 = __half22float2(h0);
    const float2 f1 = __half22float2(h1);
    a.x += f0.x; a.y += f0.y; a.z += f1.x; a.w += f1.y;
}
__device__ __forceinline__ uint2 ld_row_h(const __half* __restrict__ Wh,
                                          int s, int lane) {
    return __ldg(reinterpret_cast<const uint2*>(Wh + (size_t)s * D) + lane);
}
__device__ __forceinline__ float4 gather_rel(
    const __half* __restrict__ Wh, const int* __restrict__ srt,
    int beg, int end, int lane)
{
    float4 acc = make_float4(0.f, 0.f, 0.f, 0.f);
    int e = beg;
    for (; e + 8 <= end; e += 8) {
        int s[8];
#pragma unroll
        for (int j = 0; j < 8; j++) s[j] = __ldg(srt + e + j);
        uint2 u[8];
#pragma unroll
        for (int j = 0; j < 8; j++) u[j] = ld_row_h(Wh, s[j], lane);
#pragma unroll
        for (int j = 0; j < 8; j++) acc_u2(acc, u[j]);
    }
    if (e + 4 <= end) {
        int s[4];
#pragma unroll
        for (int j = 0; j < 4; j++) s[j] = __ldg(srt + e + j);
        uint2 u[4];
#pragma unroll
        for (int j = 0; j < 4; j++) u[j] = ld_row_h(Wh, s[j], lane);
#pragma unroll
        for (int j = 0; j < 4; j++) acc_u2(acc, u[j]);
        e += 4;
    }
    for (; e < end; e++)
        acc_u2(acc, ld_row_h(Wh, __ldg(srt + e), lane));
    return acc;
}

__global__ __launch_bounds__(256) void gather_kernel(float* __restrict__ out) {
    const int n = blockIdx.x * 8 + (threadIdx.x >> 5);
    if (n >= N_NODES) return;
    const int lane = threadIdx.x & 31;

    const int d0 = __ldg(g_cnt0 + n);
    const int d1 = __ldg(g_cnt1 + n);
    const int beg0 = n * CAP, end0 = beg0 + min(d0, CAP);
    const int beg1 = n * CAP, end1 = beg1 + min(d1, CAP);

    const float4 a0 = gather_rel(g_Wh0, g_srt0, beg0, end0, lane);
    const float4 a1 = gather_rel(g_Wh1, g_srt1, beg1, end1, lane);

    if (lane == 0) { g_cnt0[n] = 0; g_cnt1[n] = 0; }   // reset for next replay

    const float inv0 = 1.0f / fmaxf((float)d0, 1.0f);
    const float inv1 = 1.0f / fmaxf((float)d1, 1.0f);

    float4 r;
    r.x = a0.x * inv0 + a1.x * inv1;
    r.y = a0.y * inv0 + a1.y * inv1;
    r.z = a0.z * inv0 + a1.z * inv1;
    r.w = a0.w * inv0 + a1.w * inv1;
    reinterpret_cast<float4*>(out + (size_t)n * D)[lane] = r;
}

// ---------------------------------------------------------------------------
// inputs: feat, W0, b0, W1, b1, src0, dst0, src1, dst1
// ---------------------------------------------------------------------------
extern "C" void kernel_launch(void* const* d_in, const int* in_sizes, int n_in,
                              void* d_out, int out_size) {
    const float* feat = (const float*)d_in[0];
    const float* W0   = (const float*)d_in[1];
    const float* b0   = (const float*)d_in[2];
    const float* W1   = (const float*)d_in[3];
    const float* b1   = (const float*)d_in[4];
    const int*   src0 = (const int*)d_in[5];
    const int*   dst0 = (const int*)d_in[6];
    const int*   src1 = (const int*)d_in[7];
    const int*   dst1 = (const int*)d_in[8];
    float* out = (float*)d_out;

    cudaFuncSetAttribute(mma_gemm_kernel,
                         cudaFuncAttributeMaxDynamicSharedMemorySize, GEMM_SMEM);

    // Side stream: prep (W -> fp16 hi/lo) then GEMM.
    cudaEventRecord(g_st.fork, 0);
    cudaStreamWaitEvent(g_st.s1, g_st.fork, 0);
    dim3 pgrid(D * D / 256, 2);                    // (64, 2)
    prep_kernel<<<pgrid, 256, 0, g_st.s1>>>(W0, W1);
    dim3 gg(GTILES, 2);
    mma_gemm_kernel<<<gg, 256, GEMM_SMEM, g_st.s1>>>(feat, b0, b1);
    cudaEventRecord(g_st.evGemm, g_st.s1);

    // Main stream: single-kernel bucket build (both relations).
    dim3 egrid4((E_EDGES / 4 + 255) / 256, 2);
    bucket_kernel<<<egrid4, 256>>>(src0, dst0, src1, dst1);

    // Join, then gather (also resets cnt for the next replay).
    cudaStreamWaitEvent(0, g_st.evGemm, 0);
    gather_kernel<<<(N_NODES + 7) / 8, 256>>>(out);
}